// round 3
// baseline (speedup 1.0000x reference)
#include <cuda_runtime.h>

typedef unsigned long long u64;

#define NSMAX 131072
__device__ float g_p2[54 * NSMAX];   // conv output, column-major [k][sample]

__device__ __forceinline__ u64 dup2(float a) {
    u64 r;
    asm("mov.b64 %0, {%1, %1};" : "=l"(r) : "r"(__float_as_uint(a)));
    return r;
}
__device__ __forceinline__ u64 pack2(float lo, float hi) {
    u64 r;
    asm("mov.b64 %0, {%1, %2};" : "=l"(r) : "r"(__float_as_uint(lo)), "r"(__float_as_uint(hi)));
    return r;
}
__device__ __forceinline__ void fma2(u64& acc, u64 a, u64 b) {
    asm("fma.rn.f32x2 %0, %1, %2, %0;" : "+l"(acc) : "l"(a), "l"(b));
}
__device__ __forceinline__ float2 unpack2(u64 v) {
    unsigned lo, hi;
    asm("mov.b64 {%0, %1}, %2;" : "=r"(lo), "=r"(hi) : "l"(v));
    return make_float2(__uint_as_float(lo), __uint_as_float(hi));
}

// ================================================================
// Kernel 1: conv1 + pool + relu + conv2 + pool + relu  -> g_p2[k][s]
// ================================================================
#define CTPB 256

__global__ void __launch_bounds__(CTPB)
conv_kernel(const float* __restrict__ x,
            const float* __restrict__ c1w, const float* __restrict__ c1b,
            const float* __restrict__ c2w, const float* __restrict__ c2b,
            int nsamp)
{
    __shared__ float swc[198 + 10];   // c1w 27 | c1b 3 | c2w 162 | c2b 6
    const int tid = threadIdx.x;
    if (tid < 27)  swc[tid] = c1w[tid];
    if (tid < 3)   swc[27 + tid] = c1b[tid];
    if (tid < 162) swc[30 + tid] = c2w[tid];
    if (tid < 6)   swc[192 + tid] = c2b[tid];
    __syncthreads();

    const long long sample = (long long)blockIdx.x * CTPB + tid;
    if (sample >= nsamp) return;
    const float* xp = x + sample * 128;

    // ---- conv1 (1->3, 3x3 pad1 on 12x12) + maxpool2 + relu, dy-packed ----
    float c1p[3][6][6];
#pragma unroll
    for (int py = 0; py < 6; py++) {
        float ra[4][12];
#pragma unroll
        for (int j = 0; j < 4; j++) {
            const int r = 2 * py - 1 + j;
            if (r < 0 || r >= 11) {
#pragma unroll
                for (int c = 0; c < 12; c++) ra[j][c] = 0.0f;
            } else if (r == 10) {
#pragma unroll
                for (int c = 0; c < 8; c += 2) {
                    float2 v = *(const float2*)(xp + 120 + c);
                    ra[j][c] = v.x; ra[j][c + 1] = v.y;
                }
                ra[j][8] = 0.0f; ra[j][9] = 0.0f; ra[j][10] = 0.0f; ra[j][11] = 0.0f;
            } else {
#pragma unroll
                for (int c = 0; c < 12; c += 2) {
                    float2 v = *(const float2*)(xp + 12 * r + c);
                    ra[j][c] = v.x; ra[j][c + 1] = v.y;
                }
            }
        }
        u64 pr[3][12];
#pragma unroll
        for (int j = 0; j < 3; j++)
#pragma unroll
            for (int ix = 0; ix < 12; ix++)
                pr[j][ix] = pack2(ra[j][ix], ra[j + 1][ix]);

#pragma unroll
        for (int oc = 0; oc < 3; oc++) {
#pragma unroll
            for (int px = 0; px < 6; px++) {
                u64 a0 = 0ull, a1 = 0ull;
#pragma unroll
                for (int ky = 0; ky < 3; ky++) {
#pragma unroll
                    for (int kx = 0; kx < 3; kx++) {
                        const u64 wd = dup2(swc[oc * 9 + ky * 3 + kx]);
                        const int ix0 = 2 * px + kx - 1;
                        const int ix1 = 2 * px + kx;
                        if (ix0 >= 0 && ix0 < 12) fma2(a0, wd, pr[ky][ix0]);
                        if (ix1 < 12)             fma2(a1, wd, pr[ky][ix1]);
                    }
                }
                float2 v0 = unpack2(a0), v1 = unpack2(a1);
                float m = fmaxf(fmaxf(v0.x, v0.y), fmaxf(v1.x, v1.y));
                c1p[oc][py][px] = fmaxf(m + swc[27 + oc], 0.0f);
            }
        }
    }

    // ---- conv2 (3->6, 3x3 pad1 on 6x6) + maxpool2 + relu -> g_p2 ----
#pragma unroll
    for (int py = 0; py < 3; py++) {
        u64 acc[6][3][2];
#pragma unroll
        for (int oc = 0; oc < 6; oc++)
#pragma unroll
            for (int px = 0; px < 3; px++) { acc[oc][px][0] = 0ull; acc[oc][px][1] = 0ull; }

#pragma unroll
        for (int ic = 0; ic < 3; ic++) {
            u64 pc[3][6];
#pragma unroll
            for (int j = 0; j < 3; j++) {
                const int iy0 = 2 * py - 1 + j;
                const int iy1 = 2 * py + j;
#pragma unroll
                for (int ix = 0; ix < 6; ix++) {
                    const float lo = (iy0 >= 0 && iy0 < 6) ? c1p[ic][iy0][ix] : 0.0f;
                    const float hi = (iy1 < 6) ? c1p[ic][iy1][ix] : 0.0f;
                    pc[j][ix] = pack2(lo, hi);
                }
            }
#pragma unroll
            for (int oc = 0; oc < 6; oc++) {
#pragma unroll
                for (int ky = 0; ky < 3; ky++) {
#pragma unroll
                    for (int kx = 0; kx < 3; kx++) {
                        const u64 wd = dup2(swc[30 + oc * 27 + ic * 9 + ky * 3 + kx]);
#pragma unroll
                        for (int px = 0; px < 3; px++) {
                            const int ix0 = 2 * px + kx - 1;
                            const int ix1 = 2 * px + kx;
                            if (ix0 >= 0 && ix0 < 6) fma2(acc[oc][px][0], wd, pc[ky][ix0]);
                            if (ix1 < 6)             fma2(acc[oc][px][1], wd, pc[ky][ix1]);
                        }
                    }
                }
            }
        }
#pragma unroll
        for (int oc = 0; oc < 6; oc++) {
            const float bb = swc[192 + oc];
#pragma unroll
            for (int px = 0; px < 3; px++) {
                float2 v0 = unpack2(acc[oc][px][0]), v1 = unpack2(acc[oc][px][1]);
                float m = fmaxf(fmaxf(v0.x, v0.y), fmaxf(v1.x, v1.y));
                g_p2[(long long)(oc * 9 + py * 3 + px) * NSMAX + sample] = fmaxf(m + bb, 0.0f);
            }
        }
    }
}

// ================================================================
// Kernel 2: fc1 (54->128) + relu + out (128->128)   [128 samples/block]
// ================================================================
#define GTPB 512

// shared layout (floats)
#define OFF_W1D  0          // 54*128 u64 (dup'd weights) = 13824 floats
#define OFF_B1D  13824      // 128 u64 = 256 floats
#define OFF_W2T  14080      // [k][o] 128*128 = 16384
#define OFF_B2   30464      // 128
#define OFF_A    30592      // [54][132] = 7128
#define AS       132
#define OFF_H    37720      // [128][132] = 16896
#define HS       132
#define GSM_FLOATS 54616
#define GSM_BYTES (GSM_FLOATS * 4)

__global__ void __launch_bounds__(GTPB)
gemm_kernel(const float* __restrict__ w1, const float* __restrict__ b1,
            const float* __restrict__ w2, const float* __restrict__ b2,
            float* __restrict__ out, int nsamp)
{
    extern __shared__ float sm[];
    const int tid = threadIdx.x;
    const long long base = (long long)blockIdx.x * 128;

    // ---- stage: W1 dup'd [k][o], W2 transposed [k][o], biases, A tile ----
    for (int i = tid; i < 6912; i += GTPB) {
        int o = i / 54, k = i - o * 54;
        const float v = w1[i];
        sm[OFF_W1D + 2 * (k * 128 + o)]     = v;
        sm[OFF_W1D + 2 * (k * 128 + o) + 1] = v;
    }
    for (int i = tid; i < 16384; i += GTPB) {
        int o = i >> 7, k = i & 127;
        sm[OFF_W2T + k * 128 + o] = w2[i];
    }
    if (tid < 128) {
        const float v = b1[tid];
        sm[OFF_B1D + 2 * tid] = v; sm[OFF_B1D + 2 * tid + 1] = v;
        sm[OFF_B2 + tid] = b2[tid];
    }
    for (int i = tid; i < 54 * 128; i += GTPB) {
        int k = i >> 7, s = i & 127;
        sm[OFF_A + k * AS + s] = g_p2[(long long)k * NSMAX + base + s];
    }
    __syncthreads();

    const int sgrp = tid & 31;      // 32 sample-groups of 4
    const int ogrp = tid >> 5;      // 16 output-groups of 8
    const int s0 = sgrp * 4;
    const int o0 = ogrp * 8;

    // ---- fc1: acc[sample-pair][output], dup'd weights, packed samples ----
    u64 acc[2][8];
    {
        const u64* bp = (const u64*)(sm + OFF_B1D) + o0;
#pragma unroll
        for (int o = 0; o < 8; o++) { acc[0][o] = bp[o]; acc[1][o] = bp[o]; }
    }
    {
        const float* ap = sm + OFF_A + s0;
        const u64* wp = (const u64*)(sm + OFF_W1D) + o0;
#pragma unroll 3
        for (int k = 0; k < 54; k++) {
            const ulonglong2 av = *(const ulonglong2*)ap;         // 2 packed sample-pairs
            const ulonglong2 wA = *(const ulonglong2*)wp;
            const ulonglong2 wB = *(const ulonglong2*)(wp + 2);
            const ulonglong2 wC = *(const ulonglong2*)(wp + 4);
            const ulonglong2 wD = *(const ulonglong2*)(wp + 6);
            fma2(acc[0][0], av.x, wA.x); fma2(acc[1][0], av.y, wA.x);
            fma2(acc[0][1], av.x, wA.y); fma2(acc[1][1], av.y, wA.y);
            fma2(acc[0][2], av.x, wB.x); fma2(acc[1][2], av.y, wB.x);
            fma2(acc[0][3], av.x, wB.y); fma2(acc[1][3], av.y, wB.y);
            fma2(acc[0][4], av.x, wC.x); fma2(acc[1][4], av.y, wC.x);
            fma2(acc[0][5], av.x, wC.y); fma2(acc[1][5], av.y, wC.y);
            fma2(acc[0][6], av.x, wD.x); fma2(acc[1][6], av.y, wD.x);
            fma2(acc[0][7], av.x, wD.y); fma2(acc[1][7], av.y, wD.y);
            ap += AS; wp += 128;
        }
    }
    // relu -> H[o][s] (each thread stores float4 of its 4 samples per output)
#pragma unroll
    for (int o = 0; o < 8; o++) {
        float2 v0 = unpack2(acc[0][o]);
        float2 v1 = unpack2(acc[1][o]);
        float4 f;
        f.x = fmaxf(v0.x, 0.0f); f.y = fmaxf(v0.y, 0.0f);
        f.z = fmaxf(v1.x, 0.0f); f.w = fmaxf(v1.y, 0.0f);
        *(float4*)(sm + OFF_H + (o0 + o) * HS + s0) = f;
    }
    __syncthreads();

    // ---- out: acc2[sample][output-pair], packed weights, dup'd samples ----
    u64 acc2[4][4];
    {
        const u64* bp = (const u64*)(sm + OFF_B2 + o0);
#pragma unroll
        for (int i = 0; i < 4; i++) {
            acc2[i][0] = bp[0]; acc2[i][1] = bp[1];
            acc2[i][2] = bp[2]; acc2[i][3] = bp[3];
        }
    }
    {
        const float* hp = sm + OFF_H + s0;
        const float* wp = sm + OFF_W2T + o0;
#pragma unroll 2
        for (int k = 0; k < 128; k++) {
            const float4 hv = *(const float4*)hp;
            const ulonglong2 wA = *(const ulonglong2*)wp;
            const ulonglong2 wB = *(const ulonglong2*)(wp + 4);
            u64 h0 = dup2(hv.x), h1 = dup2(hv.y), h2 = dup2(hv.z), h3 = dup2(hv.w);
            fma2(acc2[0][0], h0, wA.x); fma2(acc2[0][1], h0, wA.y);
            fma2(acc2[0][2], h0, wB.x); fma2(acc2[0][3], h0, wB.y);
            fma2(acc2[1][0], h1, wA.x); fma2(acc2[1][1], h1, wA.y);
            fma2(acc2[1][2], h1, wB.x); fma2(acc2[1][3], h1, wB.y);
            fma2(acc2[2][0], h2, wA.x); fma2(acc2[2][1], h2, wA.y);
            fma2(acc2[2][2], h2, wB.x); fma2(acc2[2][3], h2, wB.y);
            fma2(acc2[3][0], h3, wA.x); fma2(acc2[3][1], h3, wA.y);
            fma2(acc2[3][2], h3, wB.x); fma2(acc2[3][3], h3, wB.y);
            hp += HS; wp += 128;
        }
    }
#pragma unroll
    for (int i = 0; i < 4; i++) {
        const long long gs = base + s0 + i;
        if (gs < nsamp) {
            float* op = out + gs * 128 + o0;
            ulonglong2 v0; v0.x = acc2[i][0]; v0.y = acc2[i][1];
            ulonglong2 v1; v1.x = acc2[i][2]; v1.y = acc2[i][3];
            *reinterpret_cast<ulonglong2*>(op)     = v0;
            *reinterpret_cast<ulonglong2*>(op + 4) = v1;
        }
    }
}

extern "C" void kernel_launch(void* const* d_in, const int* in_sizes, int n_in,
                              void* d_out, int out_size)
{
    const float* x   = (const float*)d_in[0];
    const float* c1w = (const float*)d_in[1];
    const float* c1b = (const float*)d_in[2];
    const float* c2w = (const float*)d_in[3];
    const float* c2b = (const float*)d_in[4];
    const float* w1  = (const float*)d_in[5];
    const float* b1  = (const float*)d_in[6];
    const float* w2  = (const float*)d_in[7];
    const float* b2  = (const float*)d_in[8];
    float* out = (float*)d_out;

    const int nsamp = in_sizes[0] / 128;

    const int cblocks = (nsamp + CTPB - 1) / CTPB;
    conv_kernel<<<cblocks, CTPB>>>(x, c1w, c1b, c2w, c2b, nsamp);

    const int gblocks = (nsamp + 127) / 128;
    cudaFuncSetAttribute(gemm_kernel, cudaFuncAttributeMaxDynamicSharedMemorySize, GSM_BYTES);
    gemm_kernel<<<gblocks, GTPB, GSM_BYTES>>>(w1, b1, w2, b2, out, nsamp);
}